// round 17
// baseline (speedup 1.0000x reference)
#include <cuda_runtime.h>
#include <cstdint>

#define NTOK   131072
#define DIM    1024
#define NEXP   8
#define GBATCH 4
#define NBATCH (NTOK / GBATCH)   // 32768
#define GRID   296               // persistent: 148 SMs x 2 CTAs, ONE wave
#define WT_FLOATS (NEXP * DIM)   // 8192 floats = 32KB
#define SMEM_BYTES (WT_FLOATS * 4)

__device__ __forceinline__ uint64_t pack2(float lo, float hi) {
    uint64_t r;
    asm("mov.b64 %0, {%1, %2};" : "=l"(r) : "f"(lo), "f"(hi));
    return r;
}
__device__ __forceinline__ void unpack2(uint64_t v, float& lo, float& hi) {
    asm("mov.b64 {%0, %1}, %2;" : "=f"(lo), "=f"(hi) : "l"(v));
}
// Packed dual-FMA (sm_103a): acc.lo += a.lo*b.lo; acc.hi += a.hi*b.hi
__device__ __forceinline__ void ffma2(uint64_t& acc, uint64_t a, uint64_t b) {
    asm("fma.rn.f32x2 %0, %1, %2, %0;" : "+l"(acc) : "l"(a), "l"(b));
}
// L2 prefetch: no destination register -> ptxas cannot un-pipeline it
__device__ __forceinline__ void prefetch_l2(const float* p) {
    asm volatile("prefetch.global.L2 [%0];" :: "l"(p));
}

__global__ __launch_bounds__(256, 2)
void topk_gating_kernel(const float* __restrict__ x,
                        const float* __restrict__ W,
                        const float* __restrict__ b,
                        float* __restrict__ out)
{
    extern __shared__ __align__(128) float smem[];
    float* wt = smem;                       // Wt[d][e], SW128-swizzled, 32KB

    const int tid  = threadIdx.x;
    const int lane = tid & 31;
    const int warp = tid >> 5;

    // ---- Stage W once per (persistent) CTA: [E][D] -> Wt[d][e], SW128 ----
    for (int i = tid; i < WT_FLOATS / 4; i += 256) {
        float4 v = reinterpret_cast<const float4*>(W)[i];
        int elem = i * 4;
        int e  = elem >> 10;       // expert
        int d0 = elem & 1023;      // starting d
        float vv[4] = {v.x, v.y, v.z, v.w};
        #pragma unroll
        for (int j = 0; j < 4; j++) {
            int off = (d0 + j) * 32 + e * 4;            // byte offset in Wt
            int s   = off ^ ((off >> 3) & 0x70);        // SW128 swizzle
            wt[s >> 2] = vv[j];
        }
    }
    __syncthreads();

    const int gwarp  = blockIdx.x * 8 + warp;
    const int nwarps = GRID * 8;            // 2368 warps, ~14 batches each
    const unsigned FULL = 0xffffffffu;

    const float bias = __ldg(&b[lane & 7]);

    // Per-lane swizzled smem offsets for its 4 Wt rows (8 LDS.128 per 128-d chunk)
    const int xr = (lane & 7) * 16;
    int soff[8];
    #pragma unroll
    for (int j = 0; j < 4; j++)
        #pragma unroll
        for (int c = 0; c < 2; c++)
            soff[j * 2 + c] = lane * 128 + ((j * 32 + c * 16) ^ xr);
    const char* wtb = reinterpret_cast<const char*>(wt);

    const int lo4 = lane * 4;   // this lane's float offset within a token row chunk
    // Prefetch lane mapping: lanes 0..15 each cover one 128B line of a 2KB chunk
    //   g = lane>>2 (token), line = lane&3  -> offset g*DIM + line*32 floats
    const bool pf_active = (lane < 16);
    const int  pf_off = (lane >> 2) * DIM + (lane & 3) * 32;

    int batch = gwarp;
    if (batch >= NBATCH) return;
    const float* xp  = x + (size_t)batch * GBATCH * DIM + lo4;   // consume ptr
    const float* xpb = x + (size_t)batch * GBATCH * DIM;         // prefetch base

    // ---- Prime: prefetch chunks 0,1,2 of first batch into L2 ----
    if (pf_active) {
        #pragma unroll
        for (int k = 0; k < 3; k++)
            prefetch_l2(xpb + pf_off + k * 128);
    }

    while (true) {
        const int nbatch = batch + nwarps;
        const bool has_next = (nbatch < NBATCH);
        const float* xpn  = x + (size_t)nbatch * GBATCH * DIM + lo4;
        const float* xpbn = x + (size_t)nbatch * GBATCH * DIM;

        uint64_t acc[GBATCH][4];
        #pragma unroll
        for (int g = 0; g < GBATCH; g++)
            #pragma unroll
            for (int p = 0; p < 4; p++) acc[g][p] = 0ULL;

        #pragma unroll 1
        for (int i = 0; i < 8; i++) {
            // 1) prefetch chunk i+3 into L2 (crosses into next batch at i >= 5)
            if (pf_active) {
                if (i < 5)            prefetch_l2(xpb  + pf_off + (i + 3) * 128);
                else if (has_next)    prefetch_l2(xpbn + pf_off + (i - 5) * 128);
            }

            // 2) consume x chunk i directly from gmem (L2-hit after prefetch):
            //    4 coalesced LDG.128, front-batched
            float4 xv[GBATCH];
            #pragma unroll
            for (int g = 0; g < GBATCH; g++)
                xv[g] = *reinterpret_cast<const float4*>(xp + g * DIM + i * 128);

            // 3) W pairs for this chunk: 8 LDS.128 staged up front
            ulonglong2 wq[4][2];
            #pragma unroll
            for (int j = 0; j < 4; j++)
                #pragma unroll
                for (int c = 0; c < 2; c++)
                    wq[j][c] = *reinterpret_cast<const ulonglong2*>(
                        wtb + i * 4096 + soff[j * 2 + c]);

            // 4) 64 independent FFMA2
            #pragma unroll
            for (int g = 0; g < GBATCH; g++) {
                float xsv[4] = {xv[g].x, xv[g].y, xv[g].z, xv[g].w};
                #pragma unroll
                for (int j = 0; j < 4; j++) {
                    uint64_t xpp = pack2(xsv[j], xsv[j]);
                    ffma2(acc[g][0], xpp, wq[j][0].x);
                    ffma2(acc[g][1], xpp, wq[j][0].y);
                    ffma2(acc[g][2], xpp, wq[j][1].x);
                    ffma2(acc[g][3], xpp, wq[j][1].y);
                }
            }
        }

        // ---- per-token reduce + softmax + top2 ----
        const int t0 = batch * GBATCH;
        #pragma unroll 1
        for (int g = 0; g < GBATCH; g++) {
            float q[8];
            #pragma unroll
            for (int p = 0; p < 4; p++) unpack2(acc[g][p], q[2 * p], q[2 * p + 1]);

            { // lane bit 2 fixes expert bit 2
                bool hi = (lane & 4) != 0;
                #pragma unroll
                for (int j = 0; j < 4; j++) {
                    float send = hi ? q[j] : q[j + 4];
                    float recv = __shfl_xor_sync(FULL, send, 4);
                    q[j] = (hi ? q[j + 4] : q[j]) + recv;
                }
            }
            { // lane bit 1
                bool hi = (lane & 2) != 0;
                #pragma unroll
                for (int j = 0; j < 2; j++) {
                    float send = hi ? q[j] : q[j + 2];
                    float recv = __shfl_xor_sync(FULL, send, 2);
                    q[j] = (hi ? q[j + 2] : q[j]) + recv;
                }
            }
            float v;
            { // lane bit 0
                bool hi = (lane & 1) != 0;
                float send = hi ? q[0] : q[1];
                float recv = __shfl_xor_sync(FULL, send, 1);
                v = (hi ? q[1] : q[0]) + recv;
            }
            v += __shfl_xor_sync(FULL, v, 8);
            v += __shfl_xor_sync(FULL, v, 16);
            v += bias;

            // softmax over 8 logits (replicated per octet)
            float m = v;
            m = fmaxf(m, __shfl_xor_sync(FULL, m, 1));
            m = fmaxf(m, __shfl_xor_sync(FULL, m, 2));
            m = fmaxf(m, __shfl_xor_sync(FULL, m, 4));
            float ex = __expf(v - m);
            float s = ex;
            s += __shfl_xor_sync(FULL, s, 1);
            s += __shfl_xor_sync(FULL, s, 2);
            s += __shfl_xor_sync(FULL, s, 4);
            float prob = ex / s;

            // top-2 via monotone key
            unsigned key = (__float_as_uint(prob) & ~7u) | (unsigned)(lane & 7);
            unsigned k1 = key, r;
            r = __shfl_xor_sync(FULL, k1, 1); k1 = r > k1 ? r : k1;
            r = __shfl_xor_sync(FULL, k1, 2); k1 = r > k1 ? r : k1;
            r = __shfl_xor_sync(FULL, k1, 4); k1 = r > k1 ? r : k1;
            unsigned k2 = (key == k1) ? 0u : key;
            r = __shfl_xor_sync(FULL, k2, 1); k2 = r > k2 ? r : k2;
            r = __shfl_xor_sync(FULL, k2, 2); k2 = r > k2 ? r : k2;
            r = __shfl_xor_sync(FULL, k2, 4); k2 = r > k2 ? r : k2;

            int i0 = (int)(k1 & 7u);
            int i1 = (int)(k2 & 7u);
            float v0 = __shfl_sync(FULL, prob, i0);
            float v1 = __shfl_sync(FULL, prob, i1);

            if (lane == 0) {
                int t = t0 + g;
                *reinterpret_cast<float2*>(out + 2 * t) =
                    make_float2((float)i0, (float)i1);
                *reinterpret_cast<float2*>(out + 2 * NTOK + 2 * t) =
                    make_float2(v0, v1);
            }
        }

        if (!has_next) break;
        batch = nbatch;
        xp  = xpn;
        xpb = xpbn;
    }
}

extern "C" void kernel_launch(void* const* d_in, const int* in_sizes, int n_in,
                              void* d_out, int out_size)
{
    const float* x = (const float*)d_in[0];
    const float* W = (const float*)d_in[1];
    const float* b = (const float*)d_in[2];
    float* out = (float*)d_out;
    (void)in_sizes; (void)n_in; (void)out_size;

    cudaFuncSetAttribute(topk_gating_kernel,
                         cudaFuncAttributeMaxDynamicSharedMemorySize, SMEM_BYTES);

    // Persistent single wave: 296 CTAs x 8 warps = 2368 warps, ~14 batches each
    topk_gating_kernel<<<GRID, 256, SMEM_BYTES>>>(x, W, b, out);
}